// round 6
// baseline (speedup 1.0000x reference)
#include <cuda_runtime.h>
#include <cuda_bf16.h>
#include <cstdint>

#define NB 512
#define ND 512
#define MARGIN 0.2f
#define INF_F 1e30f
#define NSPLIT 8        // K splits of 64
#define KB 64           // K per block

typedef unsigned long long ull;

// ---------------- scratch ----------------
__device__ float g_P[NSPLIT][NB * NB];   // split-K partial dot products (8 MB)

struct Ctl {
    unsigned long long acc;   // fixed-point loss sum (x 2^32)
    unsigned long long cnt;   // valid pair count
    int ready[4];             // per 128-row band: finished blocks (32 = done)
    int diagdone;             // 32 = all diagonal tiles done
    int done;                 // mining blocks finished (32)
};
__device__ Ctl g_ctl;

// ---------------- f32x2 helpers ----------------
__device__ __forceinline__ ull dup2(float x) {
    ull r;
    asm("mov.b64 %0, {%1, %1};" : "=l"(r) : "r"(__float_as_uint(x)));
    return r;
}
__device__ __forceinline__ void fma2(ull& d, ull a, ull b) {
    asm("fma.rn.f32x2 %0, %1, %2, %0;" : "+l"(d) : "l"(a), "l"(b));
}
__device__ __forceinline__ void unpk(ull v, float& lo, float& hi) {
    unsigned l, h;
    asm("mov.b64 {%0, %1}, %2;" : "=r"(l), "=r"(h) : "l"(v));
    lo = __uint_as_float(l);
    hi = __uint_as_float(h);
}

// =====================================================================
// Fused kernel. grid (4,4,8), 512 threads (16 warps -> 4 per SMSP).
//   GEMM 128x128x64 partial -> g_P[bz].
//   Warp (wr=w>>2, wc=w&3) owns 32x32; lane (ly=lane>>2, lx=lane&3)
//   owns rows wr*32+ly*4..+3, cols wc*32 + lx*4 + {0..3, 16..19}.
//   A: [k][row] f32 (32 KB). B: [k][col] PRE-DUP f32x2 ull (64 KB),
//   lane stride 32B -> conflict-free LDS.128.
// =====================================================================
__global__ void __launch_bounds__(512, 1)
k_main(const float* __restrict__ E, const int* __restrict__ labels,
       float* __restrict__ out) {
    extern __shared__ float smem[];
    float (*As)[128] = reinterpret_cast<float(*)[128]>(smem);            // 32 KB
    ull   (*Bs)[128] = reinterpret_cast<ull(*)[128]>(smem + KB * 128);   // 64 KB
    __shared__ int s_old;

    const int tid = threadIdx.x;
    const int bj = blockIdx.x, bi = blockIdx.y, bz = blockIdx.z;
    const int lane = tid & 31, warp = tid >> 5;

    // ---------- stage tiles ----------
    {
        const int r = tid & 127;          // row/col within tile
        const int q = tid >> 7;           // 0..3 -> k quarters (16 each)
        const float* Ag = E + (size_t)(bi * 128 + r) * ND + bz * KB + q * 16;
        const float* Bg = E + (size_t)(bj * 128 + r) * ND + bz * KB + q * 16;
#pragma unroll
        for (int i = 0; i < 4; i++) {
            const int k = q * 16 + i * 4;
            float4 va = *reinterpret_cast<const float4*>(Ag + i * 4);
            float4 vb = *reinterpret_cast<const float4*>(Bg + i * 4);
            As[k + 0][r] = va.x; As[k + 1][r] = va.y;
            As[k + 2][r] = va.z; As[k + 3][r] = va.w;
            Bs[k + 0][r] = dup2(vb.x); Bs[k + 1][r] = dup2(vb.y);
            Bs[k + 2][r] = dup2(vb.z); Bs[k + 3][r] = dup2(vb.w);
        }
    }
    __syncthreads();

    // ---------- compute: 4 rows x 8 cols per thread ----------
    const int wr = warp >> 2;           // 0..3
    const int wc = warp & 3;            // 0..3
    const int ly = lane >> 2;           // 0..7
    const int lx = lane & 3;            // 0..3
    const int rbase = wr * 32 + ly * 4;         // 4 rows (2 ull pairs)
    const int cb = wc * 32 + lx * 4;            // cols cb..+3 and cb+16..+19

    ull acc[2][8];
#pragma unroll
    for (int i = 0; i < 2; i++)
#pragma unroll
        for (int j = 0; j < 8; j++) acc[i][j] = 0ull;

#pragma unroll 8
    for (int kk = 0; kk < KB; kk++) {
        ull a0 = *reinterpret_cast<const ull*>(&As[kk][rbase + 0]);
        ull a1 = *reinterpret_cast<const ull*>(&As[kk][rbase + 2]);
        // 4 LDS.128, lane stride 32B -> conflict-free
        ulonglong2 b01 = *reinterpret_cast<const ulonglong2*>(&Bs[kk][cb + 0]);
        ulonglong2 b23 = *reinterpret_cast<const ulonglong2*>(&Bs[kk][cb + 2]);
        ulonglong2 b45 = *reinterpret_cast<const ulonglong2*>(&Bs[kk][cb + 16]);
        ulonglong2 b67 = *reinterpret_cast<const ulonglong2*>(&Bs[kk][cb + 18]);
        fma2(acc[0][0], a0, b01.x); fma2(acc[1][0], a1, b01.x);
        fma2(acc[0][1], a0, b01.y); fma2(acc[1][1], a1, b01.y);
        fma2(acc[0][2], a0, b23.x); fma2(acc[1][2], a1, b23.x);
        fma2(acc[0][3], a0, b23.y); fma2(acc[1][3], a1, b23.y);
        fma2(acc[0][4], a0, b45.x); fma2(acc[1][4], a1, b45.x);
        fma2(acc[0][5], a0, b45.y); fma2(acc[1][5], a1, b45.y);
        fma2(acc[0][6], a0, b67.x); fma2(acc[1][6], a1, b67.x);
        fma2(acc[0][7], a0, b67.y); fma2(acc[1][7], a1, b67.y);
    }

    // ---------- epilogue: store partial tile ----------
    {
        float* dst = g_P[bz];
        const int c0 = bj * 128 + cb;
#pragma unroll
        for (int rp = 0; rp < 2; rp++) {
            float lo[8], hi[8];
#pragma unroll
            for (int j = 0; j < 8; j++) unpk(acc[rp][j], lo[j], hi[j]);
            const int r0 = bi * 128 + rbase + 2 * rp;
            float* d0 = &dst[(size_t)r0 * NB + c0];
            float* d1 = &dst[(size_t)(r0 + 1) * NB + c0];
            *reinterpret_cast<float4*>(d0)      = make_float4(lo[0], lo[1], lo[2], lo[3]);
            *reinterpret_cast<float4*>(d0 + 16) = make_float4(lo[4], lo[5], lo[6], lo[7]);
            *reinterpret_cast<float4*>(d1)      = make_float4(hi[0], hi[1], hi[2], hi[3]);
            *reinterpret_cast<float4*>(d1 + 16) = make_float4(hi[4], hi[5], hi[6], hi[7]);
        }
    }

    __threadfence();
    __syncthreads();
    if (tid == 0) {
        if (bi == bj) atomicAdd(&g_ctl.diagdone, 1);
        s_old = atomicAdd(&g_ctl.ready[bi], 1);
    }
    __syncthreads();
    const int old = s_old;
    if (old < 24) return;              // last 8 finishers per band mine
    const int slice = old - 24;        // 0..7 -> 16 anchors each (warp per anchor)

    // wait for full band + all diagonal tiles (128 blocks wave-1 resident)
    if (tid == 0) {
        while (*(volatile int*)&g_ctl.ready[bi] < 32 ||
               *(volatile int*)&g_ctl.diagdone < 32) {}
    }
    __syncthreads();
    __threadfence();

    // ---------- mining setup: sq from GEMM diagonal, labels -> smem ----------
    float* s_sq = smem;                    // 512 floats
    int* s_lab = reinterpret_cast<int*>(smem + NB);
    for (int j = tid; j < NB; j += 512) {
        float s = 0.f;
#pragma unroll
        for (int z = 0; z < NSPLIT; z++) s += g_P[z][(size_t)j * NB + j];
        s_sq[j] = s;
        s_lab[j] = labels[j];
    }
    __syncthreads();

    // ---------- mining: warp per anchor ----------
    long long accll = 0, cntll = 0;
    {
        const int a = bi * 128 + slice * 16 + warp;
        const float sqa = s_sq[a];
        const int la = s_lab[a];

        // reg idx = g*4+e  ->  j = g*128 + lane*4 + e
        float d[16];
        int lb[16];
#pragma unroll
        for (int g = 0; g < 4; g++) {
            const int j0 = g * 128 + lane * 4;
            float4 p = make_float4(0.f, 0.f, 0.f, 0.f);
#pragma unroll
            for (int z = 0; z < NSPLIT; z++) {
                float4 v = *reinterpret_cast<const float4*>(&g_P[z][(size_t)a * NB + j0]);
                p.x += v.x; p.y += v.y; p.z += v.z; p.w += v.w;
            }
            float4 sq4 = *reinterpret_cast<const float4*>(&s_sq[j0]);
            int4 lb4 = *reinterpret_cast<const int4*>(&s_lab[j0]);
            d[g * 4 + 0] = fmaxf(sqa + sq4.x - 2.f * p.x, 0.f);
            d[g * 4 + 1] = fmaxf(sqa + sq4.y - 2.f * p.y, 0.f);
            d[g * 4 + 2] = fmaxf(sqa + sq4.z - 2.f * p.z, 0.f);
            d[g * 4 + 3] = fmaxf(sqa + sq4.w - 2.f * p.w, 0.f);
            lb[g * 4 + 0] = lb4.x; lb[g * 4 + 1] = lb4.y;
            lb[g * 4 + 2] = lb4.z; lb[g * 4 + 3] = lb4.w;
        }

        float nmin = INF_F;
#pragma unroll
        for (int t = 0; t < 16; t++)
            if (lb[t] != la) nmin = fminf(nmin, d[t]);
#pragma unroll
        for (int o = 16; o > 0; o >>= 1)
            nmin = fminf(nmin, __shfl_xor_sync(0xFFFFFFFFu, nmin, o));

        float sum = 0.f;
        int cnt = 0;
        if (nmin < 1e29f) {
#pragma unroll 1
            for (int t = 0; t < 16; t++) {
                const int j = (t >> 2) * 128 + lane * 4 + (t & 3);
                unsigned m = __ballot_sync(0xFFFFFFFFu, (j > a) && (lb[t] == la));
                while (m) {
                    const int lp = __ffs(m) - 1;
                    m &= m - 1;
                    const float ap = __shfl_sync(0xFFFFFFFFu, d[t], lp);
                    const float apM = ap + MARGIN;
                    float smin = INF_F;
#pragma unroll
                    for (int tt = 0; tt < 16; tt++) {
                        bool semi = (lb[tt] != la) && (d[tt] > ap) && (d[tt] < apM);
                        if (semi) smin = fminf(smin, d[tt]);
                    }
#pragma unroll
                    for (int o = 16; o > 0; o >>= 1)
                        smin = fminf(smin, __shfl_xor_sync(0xFFFFFFFFu, smin, o));
                    const float negd = (smin < 1e29f) ? smin : nmin;
                    sum += fmaxf(ap - negd + MARGIN, 0.f);
                    cnt++;
                }
            }
        }
        if (lane == 0) {
            accll += __double2ll_rn((double)sum * 4294967296.0);
            cntll += cnt;
        }
    }
    if (lane == 0 && (accll | cntll)) {
        atomicAdd(&g_ctl.acc, (ull)accll);
        atomicAdd(&g_ctl.cnt, (ull)cntll);
    }

    // ---------- finalize ----------
    __syncthreads();
    __threadfence();
    if (tid == 0) {
        const int o = atomicAdd(&g_ctl.done, 1);
        if (o == 31) {
            __threadfence();
            ull a = *(volatile ull*)&g_ctl.acc;
            ull c = *(volatile ull*)&g_ctl.cnt;
            out[0] = (float)(((double)a / 4294967296.0) / (double)(c ? c : 1ull));
        }
    }
}

extern "C" void kernel_launch(void* const* d_in, const int* in_sizes, int n_in,
                              void* d_out, int out_size) {
    const float* emb = (const float*)d_in[0];
    const int* labels = (const int*)d_in[1];
    float* out = (float*)d_out;

    cudaFuncSetAttribute(k_main, cudaFuncAttributeMaxDynamicSharedMemorySize,
                         100 * 1024);

    void* ctl = nullptr;
    cudaGetSymbolAddress(&ctl, g_ctl);
    cudaMemsetAsync(ctl, 0, sizeof(Ctl));

    dim3 grid(4, 4, NSPLIT);
    k_main<<<grid, 512, 96 * 1024>>>(emb, labels, out);
}

// round 7
// speedup vs baseline: 1.0046x; 1.0046x over previous
#include <cuda_runtime.h>
#include <cuda_bf16.h>
#include <cstdint>

#define NB 512
#define ND 512
#define MARGIN 0.2f
#define INF_F 1e30f
#define NSPLIT 16       // K splits of 32
#define KB 32           // K per block

typedef unsigned long long ull;

// ---------------- scratch ----------------
__device__ float g_P[NSPLIT][NB * NB];   // split-K partial dot products (16 MB)

struct Ctl {
    unsigned long long acc;   // fixed-point loss sum (x 2^32)
    unsigned long long cnt;   // valid pair count
    int ready[4];             // per 128-row band: finished blocks (64 = done)
    int diagdone;             // 64 = all diagonal tiles done
    int done;                 // mining blocks finished (64)
};
__device__ Ctl g_ctl;

// ---------------- f32x2 helpers ----------------
__device__ __forceinline__ ull dup2(float x) {
    ull r;
    asm("mov.b64 %0, {%1, %1};" : "=l"(r) : "r"(__float_as_uint(x)));
    return r;
}
__device__ __forceinline__ void fma2(ull& d, ull a, ull b) {
    asm("fma.rn.f32x2 %0, %1, %2, %0;" : "+l"(d) : "l"(a), "l"(b));
}
__device__ __forceinline__ void unpk(ull v, float& lo, float& hi) {
    unsigned l, h;
    asm("mov.b64 {%0, %1}, %2;" : "=r"(l), "=r"(h) : "l"(v));
    lo = __uint_as_float(l);
    hi = __uint_as_float(h);
}

// =====================================================================
// Fused kernel. grid (4,4,16), 256 threads, 2 blocks/SM.
//   GEMM 128x128x32 partial -> g_P[bz]. R5 warp layout (best FFMA:LDS):
//   warp (wr=w>>1, wc=w&1) owns 32x64; lane (ly=lane>>3, lx=lane&7)
//   owns rows wr*32+ly*8..+7, cols wc*64 + {lx*4..+3, 32+lx*4..+3}.
// =====================================================================
__global__ void __launch_bounds__(256, 2)
k_main(const float* __restrict__ E, const int* __restrict__ labels,
       float* __restrict__ out) {
    __shared__ float As[KB][128];   // 16 KB [k][row]
    __shared__ float Bs[KB][128];   // 16 KB [k][col]
    __shared__ int s_old;

    const int tid = threadIdx.x;
    const int bj = blockIdx.x, bi = blockIdx.y, bz = blockIdx.z;
    const int lane = tid & 31, warp = tid >> 5;

    // ---------- stage tiles (transposed, conflict-free) ----------
    {
        const int r = tid & 127;
        const int h = tid >> 7;                  // 0/1 -> k halves of 16
        const float* Ag = E + (size_t)(bi * 128 + r) * ND + bz * KB + h * 16;
        const float* Bg = E + (size_t)(bj * 128 + r) * ND + bz * KB + h * 16;
#pragma unroll
        for (int i = 0; i < 4; i++) {
            const int k = h * 16 + i * 4;
            float4 va = *reinterpret_cast<const float4*>(Ag + i * 4);
            float4 vb = *reinterpret_cast<const float4*>(Bg + i * 4);
            As[k + 0][r] = va.x; As[k + 1][r] = va.y;
            As[k + 2][r] = va.z; As[k + 3][r] = va.w;
            Bs[k + 0][r] = vb.x; Bs[k + 1][r] = vb.y;
            Bs[k + 2][r] = vb.z; Bs[k + 3][r] = vb.w;
        }
    }
    __syncthreads();

    // ---------- compute: 8x8 per thread ----------
    const int wr = warp >> 1;          // 0..3
    const int wc = warp & 1;           // 0..1
    const int ly = lane >> 3;          // 0..3
    const int lx = lane & 7;           // 0..7
    const int rbase = wr * 32 + ly * 8;
    const int cbase = wc * 64 + lx * 4;

    ull acc[4][8];
#pragma unroll
    for (int i = 0; i < 4; i++)
#pragma unroll
        for (int j = 0; j < 8; j++) acc[i][j] = 0ull;

#pragma unroll 4
    for (int kk = 0; kk < KB; kk++) {
        ull a0 = *reinterpret_cast<const ull*>(&As[kk][rbase + 0]);
        ull a1 = *reinterpret_cast<const ull*>(&As[kk][rbase + 2]);
        ull a2 = *reinterpret_cast<const ull*>(&As[kk][rbase + 4]);
        ull a3 = *reinterpret_cast<const ull*>(&As[kk][rbase + 6]);
        // batch 0: cols cbase..+3
        {
            float4 bv = *reinterpret_cast<const float4*>(&Bs[kk][cbase]);
            ull b0 = dup2(bv.x), b1 = dup2(bv.y), b2 = dup2(bv.z), b3 = dup2(bv.w);
            fma2(acc[0][0], a0, b0); fma2(acc[1][0], a1, b0);
            fma2(acc[2][0], a2, b0); fma2(acc[3][0], a3, b0);
            fma2(acc[0][1], a0, b1); fma2(acc[1][1], a1, b1);
            fma2(acc[2][1], a2, b1); fma2(acc[3][1], a3, b1);
            fma2(acc[0][2], a0, b2); fma2(acc[1][2], a1, b2);
            fma2(acc[2][2], a2, b2); fma2(acc[3][2], a3, b2);
            fma2(acc[0][3], a0, b3); fma2(acc[1][3], a1, b3);
            fma2(acc[2][3], a2, b3); fma2(acc[3][3], a3, b3);
        }
        // batch 1: cols cbase+32..+35
        {
            float4 bv = *reinterpret_cast<const float4*>(&Bs[kk][cbase + 32]);
            ull b0 = dup2(bv.x), b1 = dup2(bv.y), b2 = dup2(bv.z), b3 = dup2(bv.w);
            fma2(acc[0][4], a0, b0); fma2(acc[1][4], a1, b0);
            fma2(acc[2][4], a2, b0); fma2(acc[3][4], a3, b0);
            fma2(acc[0][5], a0, b1); fma2(acc[1][5], a1, b1);
            fma2(acc[2][5], a2, b1); fma2(acc[3][5], a3, b1);
            fma2(acc[0][6], a0, b2); fma2(acc[1][6], a1, b2);
            fma2(acc[2][6], a2, b2); fma2(acc[3][6], a3, b2);
            fma2(acc[0][7], a0, b3); fma2(acc[1][7], a1, b3);
            fma2(acc[2][7], a2, b3); fma2(acc[3][7], a3, b3);
        }
    }

    // ---------- epilogue: store partial tile ----------
    {
        float* dst = g_P[bz];
        const int c0 = bj * 128 + cbase;
#pragma unroll
        for (int rp = 0; rp < 4; rp++) {
            float lo[8], hi[8];
#pragma unroll
            for (int j = 0; j < 8; j++) unpk(acc[rp][j], lo[j], hi[j]);
            const int r0 = bi * 128 + rbase + 2 * rp;
            float* d0 = &dst[(size_t)r0 * NB + c0];
            float* d1 = &dst[(size_t)(r0 + 1) * NB + c0];
            *reinterpret_cast<float4*>(d0)      = make_float4(lo[0], lo[1], lo[2], lo[3]);
            *reinterpret_cast<float4*>(d0 + 32) = make_float4(lo[4], lo[5], lo[6], lo[7]);
            *reinterpret_cast<float4*>(d1)      = make_float4(hi[0], hi[1], hi[2], hi[3]);
            *reinterpret_cast<float4*>(d1 + 32) = make_float4(hi[4], hi[5], hi[6], hi[7]);
        }
    }

    __threadfence();
    __syncthreads();
    if (tid == 0) {
        if (bi == bj) atomicAdd(&g_ctl.diagdone, 1);
        s_old = atomicAdd(&g_ctl.ready[bi], 1);
    }
    __syncthreads();
    const int old = s_old;
    if (old < 48) return;              // last 16 finishers per band mine
    const int slice = old - 48;        // 0..15 -> 8 anchors each (warp per anchor)

    // wait for full band + all diagonal tiles (256 blocks, 2/SM, all resident)
    if (tid == 0) {
        while (*(volatile int*)&g_ctl.ready[bi] < 64 ||
               *(volatile int*)&g_ctl.diagdone < 64) {}
    }
    __syncthreads();
    __threadfence();

    // ---------- mining setup: sq from GEMM diagonal, labels -> smem ----------
    float* s_sq = &As[0][0];               // 512 floats
    int* s_lab = reinterpret_cast<int*>(&Bs[0][0]);
    for (int j = tid; j < NB; j += 256) {
        float s = 0.f;
#pragma unroll
        for (int z = 0; z < NSPLIT; z++) s += g_P[z][(size_t)j * NB + j];
        s_sq[j] = s;
        s_lab[j] = labels[j];
    }
    __syncthreads();

    // ---------- mining: warp per anchor ----------
    long long accll = 0, cntll = 0;
    {
        const int a = bi * 128 + slice * 8 + warp;
        const float sqa = s_sq[a];
        const int la = s_lab[a];

        // reg idx = g*4+e  ->  j = g*128 + lane*4 + e
        float d[16];
        int lb[16];
#pragma unroll
        for (int g = 0; g < 4; g++) {
            const int j0 = g * 128 + lane * 4;
            float4 p = make_float4(0.f, 0.f, 0.f, 0.f);
#pragma unroll
            for (int z = 0; z < NSPLIT; z++) {
                float4 v = *reinterpret_cast<const float4*>(&g_P[z][(size_t)a * NB + j0]);
                p.x += v.x; p.y += v.y; p.z += v.z; p.w += v.w;
            }
            float4 sq4 = *reinterpret_cast<const float4*>(&s_sq[j0]);
            int4 lb4 = *reinterpret_cast<const int4*>(&s_lab[j0]);
            d[g * 4 + 0] = fmaxf(sqa + sq4.x - 2.f * p.x, 0.f);
            d[g * 4 + 1] = fmaxf(sqa + sq4.y - 2.f * p.y, 0.f);
            d[g * 4 + 2] = fmaxf(sqa + sq4.z - 2.f * p.z, 0.f);
            d[g * 4 + 3] = fmaxf(sqa + sq4.w - 2.f * p.w, 0.f);
            lb[g * 4 + 0] = lb4.x; lb[g * 4 + 1] = lb4.y;
            lb[g * 4 + 2] = lb4.z; lb[g * 4 + 3] = lb4.w;
        }

        float nmin = INF_F;
#pragma unroll
        for (int t = 0; t < 16; t++)
            if (lb[t] != la) nmin = fminf(nmin, d[t]);
#pragma unroll
        for (int o = 16; o > 0; o >>= 1)
            nmin = fminf(nmin, __shfl_xor_sync(0xFFFFFFFFu, nmin, o));

        float sum = 0.f;
        int cnt = 0;
        if (nmin < 1e29f) {
#pragma unroll 1
            for (int t = 0; t < 16; t++) {
                const int j = (t >> 2) * 128 + lane * 4 + (t & 3);
                unsigned m = __ballot_sync(0xFFFFFFFFu, (j > a) && (lb[t] == la));
                while (m) {
                    const int lp = __ffs(m) - 1;
                    m &= m - 1;
                    const float ap = __shfl_sync(0xFFFFFFFFu, d[t], lp);
                    const float apM = ap + MARGIN;
                    float smin = INF_F;
#pragma unroll
                    for (int tt = 0; tt < 16; tt++) {
                        bool semi = (lb[tt] != la) && (d[tt] > ap) && (d[tt] < apM);
                        if (semi) smin = fminf(smin, d[tt]);
                    }
#pragma unroll
                    for (int o = 16; o > 0; o >>= 1)
                        smin = fminf(smin, __shfl_xor_sync(0xFFFFFFFFu, smin, o));
                    const float negd = (smin < 1e29f) ? smin : nmin;
                    sum += fmaxf(ap - negd + MARGIN, 0.f);
                    cnt++;
                }
            }
        }
        if (lane == 0) {
            accll += __double2ll_rn((double)sum * 4294967296.0);
            cntll += cnt;
        }
    }
    if (lane == 0 && (accll | cntll)) {
        atomicAdd(&g_ctl.acc, (ull)accll);
        atomicAdd(&g_ctl.cnt, (ull)cntll);
    }

    // ---------- finalize ----------
    __syncthreads();
    __threadfence();
    if (tid == 0) {
        const int o = atomicAdd(&g_ctl.done, 1);
        if (o == 63) {
            __threadfence();
            ull a = *(volatile ull*)&g_ctl.acc;
            ull c = *(volatile ull*)&g_ctl.cnt;
            out[0] = (float)(((double)a / 4294967296.0) / (double)(c ? c : 1ull));
        }
    }
}

extern "C" void kernel_launch(void* const* d_in, const int* in_sizes, int n_in,
                              void* d_out, int out_size) {
    const float* emb = (const float*)d_in[0];
    const int* labels = (const int*)d_in[1];
    float* out = (float*)d_out;

    void* ctl = nullptr;
    cudaGetSymbolAddress(&ctl, g_ctl);
    cudaMemsetAsync(ctl, 0, sizeof(Ctl));

    dim3 grid(4, 4, NSPLIT);
    k_main<<<grid, 256>>>(emb, labels, out);
}

// round 8
// speedup vs baseline: 1.0674x; 1.0625x over previous
#include <cuda_runtime.h>
#include <cuda_bf16.h>
#include <cstdint>

#define NB 512
#define ND 512
#define MARGIN 0.2f
#define INF_F 1e30f
#define NSPLIT 8        // K splits of 64
#define KB 64           // K per block

typedef unsigned long long ull;

// ---------------- scratch ----------------
__device__ float g_P[NSPLIT][NB * NB];   // split-K partial dot products (8 MB)

struct Ctl {
    unsigned long long acc;   // fixed-point loss sum (x 2^32)
    unsigned long long cnt;   // valid pair count
    int done;                 // mining blocks finished (64)
    int pad;
};
__device__ Ctl g_ctl;

// ---------------- f32x2 helpers ----------------
__device__ __forceinline__ ull dup2(float x) {
    ull r;
    asm("mov.b64 %0, {%1, %1};" : "=l"(r) : "r"(__float_as_uint(x)));
    return r;
}
__device__ __forceinline__ void fma2(ull& d, ull a, ull b) {
    asm("fma.rn.f32x2 %0, %1, %2, %0;" : "+l"(d) : "l"(a), "l"(b));
}
__device__ __forceinline__ void unpk(ull v, float& lo, float& hi) {
    unsigned l, h;
    asm("mov.b64 {%0, %1}, %2;" : "=r"(l), "=r"(h) : "l"(v));
    lo = __uint_as_float(l);
    hi = __uint_as_float(h);
}

// =====================================================================
// Kernel A: GEMM only. grid (4,4,8), 256 threads, 96KB smem.
//   R5 warp layout: warp (wr=w>>1, wc=w&1) owns 32x64;
//   lane (ly=lane>>3, lx=lane&7): rows wr*32+ly*8..+7,
//   cols wc*64 + {lx*4..+3, 32+lx*4..+3}.
//   A: [k][row] f32 (32KB). B: [k][col] PRE-DUP f32x2 (64KB).
// =====================================================================
__global__ void __launch_bounds__(256, 1)
k_gemm(const float* __restrict__ E) {
    extern __shared__ float smem[];
    float (*As)[128] = reinterpret_cast<float(*)[128]>(smem);              // 32 KB
    ull   (*Bs)[128] = reinterpret_cast<ull(*)[128]>(smem + KB * 128);     // 64 KB

    const int tid = threadIdx.x;
    const int bj = blockIdx.x, bi = blockIdx.y, bz = blockIdx.z;
    const int lane = tid & 31, warp = tid >> 5;

    // ---------- stage tiles ----------
    {
        const int r = tid & 127;
        const int half = tid >> 7;                 // 0/1 -> k halves of 32
        const float* Ag = E + (size_t)(bi * 128 + r) * ND + bz * KB + half * 32;
        const float* Bg = E + (size_t)(bj * 128 + r) * ND + bz * KB + half * 32;
#pragma unroll
        for (int i = 0; i < 8; i++) {
            const int k = half * 32 + i * 4;
            float4 va = *reinterpret_cast<const float4*>(Ag + i * 4);
            float4 vb = *reinterpret_cast<const float4*>(Bg + i * 4);
            As[k + 0][r] = va.x; As[k + 1][r] = va.y;
            As[k + 2][r] = va.z; As[k + 3][r] = va.w;
            Bs[k + 0][r] = dup2(vb.x); Bs[k + 1][r] = dup2(vb.y);
            Bs[k + 2][r] = dup2(vb.z); Bs[k + 3][r] = dup2(vb.w);
        }
    }
    __syncthreads();

    // ---------- compute: 8x8 per thread ----------
    const int wr = warp >> 1, wc = warp & 1;
    const int ly = lane >> 3, lx = lane & 7;
    const int rbase = wr * 32 + ly * 8;
    const int cbase = wc * 64 + lx * 4;

    ull acc[4][8];
#pragma unroll
    for (int i = 0; i < 4; i++)
#pragma unroll
        for (int j = 0; j < 8; j++) acc[i][j] = 0ull;

#pragma unroll 4
    for (int kk = 0; kk < KB; kk++) {
        // A: 2x LDS.128 (4 row-pair ulls), 8-lane broadcast groups
        ulonglong2 A01 = *reinterpret_cast<const ulonglong2*>(&As[kk][rbase + 0]);
        ulonglong2 A23 = *reinterpret_cast<const ulonglong2*>(&As[kk][rbase + 4]);
        // B: 4x LDS.128 pre-dup'd f32x2, 32B lane stride -> conflict-free
        ulonglong2 B01 = *reinterpret_cast<const ulonglong2*>(&Bs[kk][cbase + 0]);
        ulonglong2 B23 = *reinterpret_cast<const ulonglong2*>(&Bs[kk][cbase + 2]);
        ulonglong2 B45 = *reinterpret_cast<const ulonglong2*>(&Bs[kk][cbase + 32]);
        ulonglong2 B67 = *reinterpret_cast<const ulonglong2*>(&Bs[kk][cbase + 34]);
        fma2(acc[0][0], A01.x, B01.x); fma2(acc[1][0], A01.y, B01.x);
        fma2(acc[2][0], A23.x, B01.x); fma2(acc[3][0], A23.y, B01.x);
        fma2(acc[0][1], A01.x, B01.y); fma2(acc[1][1], A01.y, B01.y);
        fma2(acc[2][1], A23.x, B01.y); fma2(acc[3][1], A23.y, B01.y);
        fma2(acc[0][2], A01.x, B23.x); fma2(acc[1][2], A01.y, B23.x);
        fma2(acc[2][2], A23.x, B23.x); fma2(acc[3][2], A23.y, B23.x);
        fma2(acc[0][3], A01.x, B23.y); fma2(acc[1][3], A01.y, B23.y);
        fma2(acc[2][3], A23.x, B23.y); fma2(acc[3][3], A23.y, B23.y);
        fma2(acc[0][4], A01.x, B45.x); fma2(acc[1][4], A01.y, B45.x);
        fma2(acc[2][4], A23.x, B45.x); fma2(acc[3][4], A23.y, B45.x);
        fma2(acc[0][5], A01.x, B45.y); fma2(acc[1][5], A01.y, B45.y);
        fma2(acc[2][5], A23.x, B45.y); fma2(acc[3][5], A23.y, B45.y);
        fma2(acc[0][6], A01.x, B67.x); fma2(acc[1][6], A01.y, B67.x);
        fma2(acc[2][6], A23.x, B67.x); fma2(acc[3][6], A23.y, B67.x);
        fma2(acc[0][7], A01.x, B67.y); fma2(acc[1][7], A01.y, B67.y);
        fma2(acc[2][7], A23.x, B67.y); fma2(acc[3][7], A23.y, B67.y);
    }

    // ---------- epilogue: store partial tile ----------
    {
        float* dst = g_P[bz];
        const int c0 = bj * 128 + cbase;
#pragma unroll
        for (int rp = 0; rp < 4; rp++) {
            float lo[8], hi[8];
#pragma unroll
            for (int j = 0; j < 8; j++) unpk(acc[rp][j], lo[j], hi[j]);
            const int r0 = bi * 128 + rbase + 2 * rp;
            float* d0 = &dst[(size_t)r0 * NB + c0];
            float* d1 = &dst[(size_t)(r0 + 1) * NB + c0];
            *reinterpret_cast<float4*>(d0)      = make_float4(lo[0], lo[1], lo[2], lo[3]);
            *reinterpret_cast<float4*>(d0 + 32) = make_float4(lo[4], lo[5], lo[6], lo[7]);
            *reinterpret_cast<float4*>(d1)      = make_float4(hi[0], hi[1], hi[2], hi[3]);
            *reinterpret_cast<float4*>(d1 + 32) = make_float4(hi[4], hi[5], hi[6], hi[7]);
        }
    }
}

// =====================================================================
// Kernel B: semi-hard mining + finalize. grid 64 x 256 (warp per anchor).
// =====================================================================
__global__ void __launch_bounds__(256, 1)
k_mine(const int* __restrict__ labels, float* __restrict__ out) {
    __shared__ float s_sq[NB];
    __shared__ int s_lab[NB];

    const int tid = threadIdx.x;
    const int lane = tid & 31, warp = tid >> 5;

    // sq from GEMM diagonal, labels -> smem
    for (int j = tid; j < NB; j += 256) {
        float s = 0.f;
#pragma unroll
        for (int z = 0; z < NSPLIT; z++) s += g_P[z][(size_t)j * NB + j];
        s_sq[j] = s;
        s_lab[j] = labels[j];
    }
    __syncthreads();

    long long accll = 0, cntll = 0;
    {
        const int a = blockIdx.x * 8 + warp;
        const float sqa = s_sq[a];
        const int la = s_lab[a];

        // reg idx = g*4+e  ->  j = g*128 + lane*4 + e
        float d[16];
        int lb[16];
#pragma unroll
        for (int g = 0; g < 4; g++) {
            const int j0 = g * 128 + lane * 4;
            float4 p = make_float4(0.f, 0.f, 0.f, 0.f);
#pragma unroll
            for (int z = 0; z < NSPLIT; z++) {
                float4 v = *reinterpret_cast<const float4*>(&g_P[z][(size_t)a * NB + j0]);
                p.x += v.x; p.y += v.y; p.z += v.z; p.w += v.w;
            }
            float4 sq4 = *reinterpret_cast<const float4*>(&s_sq[j0]);
            int4 lb4 = *reinterpret_cast<const int4*>(&s_lab[j0]);
            d[g * 4 + 0] = fmaxf(sqa + sq4.x - 2.f * p.x, 0.f);
            d[g * 4 + 1] = fmaxf(sqa + sq4.y - 2.f * p.y, 0.f);
            d[g * 4 + 2] = fmaxf(sqa + sq4.z - 2.f * p.z, 0.f);
            d[g * 4 + 3] = fmaxf(sqa + sq4.w - 2.f * p.w, 0.f);
            lb[g * 4 + 0] = lb4.x; lb[g * 4 + 1] = lb4.y;
            lb[g * 4 + 2] = lb4.z; lb[g * 4 + 3] = lb4.w;
        }

        float nmin = INF_F;
#pragma unroll
        for (int t = 0; t < 16; t++)
            if (lb[t] != la) nmin = fminf(nmin, d[t]);
#pragma unroll
        for (int o = 16; o > 0; o >>= 1)
            nmin = fminf(nmin, __shfl_xor_sync(0xFFFFFFFFu, nmin, o));

        float sum = 0.f;
        int cnt = 0;
        if (nmin < 1e29f) {
#pragma unroll 1
            for (int t = 0; t < 16; t++) {
                const int j = (t >> 2) * 128 + lane * 4 + (t & 3);
                unsigned m = __ballot_sync(0xFFFFFFFFu, (j > a) && (lb[t] == la));
                while (m) {
                    const int lp = __ffs(m) - 1;
                    m &= m - 1;
                    const float ap = __shfl_sync(0xFFFFFFFFu, d[t], lp);
                    const float apM = ap + MARGIN;
                    float smin = INF_F;
#pragma unroll
                    for (int tt = 0; tt < 16; tt++) {
                        bool semi = (lb[tt] != la) && (d[tt] > ap) && (d[tt] < apM);
                        if (semi) smin = fminf(smin, d[tt]);
                    }
#pragma unroll
                    for (int o = 16; o > 0; o >>= 1)
                        smin = fminf(smin, __shfl_xor_sync(0xFFFFFFFFu, smin, o));
                    const float negd = (smin < 1e29f) ? smin : nmin;
                    sum += fmaxf(ap - negd + MARGIN, 0.f);
                    cnt++;
                }
            }
        }
        if (lane == 0) {
            accll = __double2ll_rn((double)sum * 4294967296.0);
            cntll = cnt;
        }
    }
    if (lane == 0 && (accll | cntll)) {
        atomicAdd(&g_ctl.acc, (ull)accll);
        atomicAdd(&g_ctl.cnt, (ull)cntll);
    }

    // finalize: last block writes the scalar
    __syncthreads();
    __threadfence();
    if (tid == 0) {
        const int o = atomicAdd(&g_ctl.done, 1);
        if (o == 63) {
            __threadfence();
            ull a = *(volatile ull*)&g_ctl.acc;
            ull c = *(volatile ull*)&g_ctl.cnt;
            out[0] = (float)(((double)a / 4294967296.0) / (double)(c ? c : 1ull));
        }
    }
}

extern "C" void kernel_launch(void* const* d_in, const int* in_sizes, int n_in,
                              void* d_out, int out_size) {
    const float* emb = (const float*)d_in[0];
    const int* labels = (const int*)d_in[1];
    float* out = (float*)d_out;

    cudaFuncSetAttribute(k_gemm, cudaFuncAttributeMaxDynamicSharedMemorySize,
                         100 * 1024);

    void* ctl = nullptr;
    cudaGetSymbolAddress(&ctl, g_ctl);
    cudaMemsetAsync(ctl, 0, sizeof(Ctl));

    dim3 grid(4, 4, NSPLIT);
    k_gemm<<<grid, 256, 96 * 1024>>>(emb);
    k_mine<<<64, 256>>>(labels, out);
}

// round 9
// speedup vs baseline: 1.0758x; 1.0079x over previous
#include <cuda_runtime.h>
#include <cuda_bf16.h>
#include <cstdint>

#define NB 512
#define ND 512
#define MARGIN 0.2f
#define INF_F 1e30f
#define NSPLIT 8        // K splits of 64
#define KB 64           // K per block

typedef unsigned long long ull;

// ---------------- scratch ----------------
__device__ float g_P[NSPLIT][NB * NB];   // split-K partial dot products (8 MB)
__device__ float g_Dm[NB * NB];          // reduced dot products (1 MB)
__device__ float g_sq[NB];               // row squared norms (diag of g_Dm)

struct Ctl {
    unsigned long long acc;   // fixed-point loss sum (x 2^32)
    unsigned long long cnt;   // valid pair count
    int done;
    int pad;
};
__device__ Ctl g_ctl;

// ---------------- f32x2 helpers ----------------
__device__ __forceinline__ ull dup2(float x) {
    ull r;
    asm("mov.b64 %0, {%1, %1};" : "=l"(r) : "r"(__float_as_uint(x)));
    return r;
}
__device__ __forceinline__ void fma2(ull& d, ull a, ull b) {
    asm("fma.rn.f32x2 %0, %1, %2, %0;" : "+l"(d) : "l"(a), "l"(b));
}
__device__ __forceinline__ void unpk(ull v, float& lo, float& hi) {
    unsigned l, h;
    asm("mov.b64 {%0, %1}, %2;" : "=r"(l), "=r"(h) : "l"(v));
    lo = __uint_as_float(l);
    hi = __uint_as_float(h);
}

// =====================================================================
// Kernel A: GEMM. grid (4,4,8), 256 threads, 96KB smem. (R8-validated)
// =====================================================================
__global__ void __launch_bounds__(256, 1)
k_gemm(const float* __restrict__ E) {
    extern __shared__ float smem[];
    float (*As)[128] = reinterpret_cast<float(*)[128]>(smem);              // 32 KB
    ull   (*Bs)[128] = reinterpret_cast<ull(*)[128]>(smem + KB * 128);     // 64 KB

    const int tid = threadIdx.x;
    const int bj = blockIdx.x, bi = blockIdx.y, bz = blockIdx.z;
    const int lane = tid & 31, warp = tid >> 5;

    {
        const int r = tid & 127;
        const int half = tid >> 7;
        const float* Ag = E + (size_t)(bi * 128 + r) * ND + bz * KB + half * 32;
        const float* Bg = E + (size_t)(bj * 128 + r) * ND + bz * KB + half * 32;
#pragma unroll
        for (int i = 0; i < 8; i++) {
            const int k = half * 32 + i * 4;
            float4 va = *reinterpret_cast<const float4*>(Ag + i * 4);
            float4 vb = *reinterpret_cast<const float4*>(Bg + i * 4);
            As[k + 0][r] = va.x; As[k + 1][r] = va.y;
            As[k + 2][r] = va.z; As[k + 3][r] = va.w;
            Bs[k + 0][r] = dup2(vb.x); Bs[k + 1][r] = dup2(vb.y);
            Bs[k + 2][r] = dup2(vb.z); Bs[k + 3][r] = dup2(vb.w);
        }
    }
    __syncthreads();

    const int wr = warp >> 1, wc = warp & 1;
    const int ly = lane >> 3, lx = lane & 7;
    const int rbase = wr * 32 + ly * 8;
    const int cbase = wc * 64 + lx * 4;

    ull acc[4][8];
#pragma unroll
    for (int i = 0; i < 4; i++)
#pragma unroll
        for (int j = 0; j < 8; j++) acc[i][j] = 0ull;

#pragma unroll 4
    for (int kk = 0; kk < KB; kk++) {
        ulonglong2 A01 = *reinterpret_cast<const ulonglong2*>(&As[kk][rbase + 0]);
        ulonglong2 A23 = *reinterpret_cast<const ulonglong2*>(&As[kk][rbase + 4]);
        ulonglong2 B01 = *reinterpret_cast<const ulonglong2*>(&Bs[kk][cbase + 0]);
        ulonglong2 B23 = *reinterpret_cast<const ulonglong2*>(&Bs[kk][cbase + 2]);
        ulonglong2 B45 = *reinterpret_cast<const ulonglong2*>(&Bs[kk][cbase + 32]);
        ulonglong2 B67 = *reinterpret_cast<const ulonglong2*>(&Bs[kk][cbase + 34]);
        fma2(acc[0][0], A01.x, B01.x); fma2(acc[1][0], A01.y, B01.x);
        fma2(acc[2][0], A23.x, B01.x); fma2(acc[3][0], A23.y, B01.x);
        fma2(acc[0][1], A01.x, B01.y); fma2(acc[1][1], A01.y, B01.y);
        fma2(acc[2][1], A23.x, B01.y); fma2(acc[3][1], A23.y, B01.y);
        fma2(acc[0][2], A01.x, B23.x); fma2(acc[1][2], A01.y, B23.x);
        fma2(acc[2][2], A23.x, B23.x); fma2(acc[3][2], A23.y, B23.x);
        fma2(acc[0][3], A01.x, B23.y); fma2(acc[1][3], A01.y, B23.y);
        fma2(acc[2][3], A23.x, B23.y); fma2(acc[3][3], A23.y, B23.y);
        fma2(acc[0][4], A01.x, B45.x); fma2(acc[1][4], A01.y, B45.x);
        fma2(acc[2][4], A23.x, B45.x); fma2(acc[3][4], A23.y, B45.x);
        fma2(acc[0][5], A01.x, B45.y); fma2(acc[1][5], A01.y, B45.y);
        fma2(acc[2][5], A23.x, B45.y); fma2(acc[3][5], A23.y, B45.y);
        fma2(acc[0][6], A01.x, B67.x); fma2(acc[1][6], A01.y, B67.x);
        fma2(acc[2][6], A23.x, B67.x); fma2(acc[3][6], A23.y, B67.x);
        fma2(acc[0][7], A01.x, B67.y); fma2(acc[1][7], A01.y, B67.y);
        fma2(acc[2][7], A23.x, B67.y); fma2(acc[3][7], A23.y, B67.y);
    }

    {
        float* dst = g_P[bz];
        const int c0 = bj * 128 + cbase;
#pragma unroll
        for (int rp = 0; rp < 4; rp++) {
            float lo[8], hi[8];
#pragma unroll
            for (int j = 0; j < 8; j++) unpk(acc[rp][j], lo[j], hi[j]);
            const int r0 = bi * 128 + rbase + 2 * rp;
            float* d0 = &dst[(size_t)r0 * NB + c0];
            float* d1 = &dst[(size_t)(r0 + 1) * NB + c0];
            *reinterpret_cast<float4*>(d0)      = make_float4(lo[0], lo[1], lo[2], lo[3]);
            *reinterpret_cast<float4*>(d0 + 32) = make_float4(lo[4], lo[5], lo[6], lo[7]);
            *reinterpret_cast<float4*>(d1)      = make_float4(hi[0], hi[1], hi[2], hi[3]);
            *reinterpret_cast<float4*>(d1 + 32) = make_float4(hi[4], hi[5], hi[6], hi[7]);
        }
    }
}

// =====================================================================
// Kernel B: reduce 8 splits -> g_Dm, extract diag -> g_sq.
//   grid 512 (one block per row), 128 threads (4 cols each via float4).
// =====================================================================
__global__ void __launch_bounds__(128, 8)
k_prep(void) {
    const int r = blockIdx.x;
    const int tid = threadIdx.x;
    const size_t rowoff = (size_t)r * NB + tid * 4;

    float4 s = make_float4(0.f, 0.f, 0.f, 0.f);
#pragma unroll
    for (int z = 0; z < NSPLIT; z++) {
        float4 v = *reinterpret_cast<const float4*>(&g_P[z][rowoff]);
        s.x += v.x; s.y += v.y; s.z += v.z; s.w += v.w;
    }
    *reinterpret_cast<float4*>(&g_Dm[rowoff]) = s;

    // diagonal element -> g_sq[r]
    const int dcol = r >> 2;          // thread holding column r
    const int dsub = r & 3;
    if (tid == dcol) {
        float dv = (dsub == 0) ? s.x : (dsub == 1) ? s.y : (dsub == 2) ? s.z : s.w;
        g_sq[r] = dv;
    }
}

// =====================================================================
// Kernel C: semi-hard mining + finalize. grid 64 x 256 (warp per anchor).
//   Reads reduced g_Dm only (2KB per anchor).
// =====================================================================
__global__ void __launch_bounds__(256, 1)
k_mine(const int* __restrict__ labels, float* __restrict__ out) {
    __shared__ float s_sq[NB];
    __shared__ int s_lab[NB];

    const int tid = threadIdx.x;
    const int lane = tid & 31, warp = tid >> 5;

    for (int j = tid; j < NB; j += 256) {
        s_sq[j] = g_sq[j];
        s_lab[j] = labels[j];
    }
    __syncthreads();

    long long accll = 0, cntll = 0;
    {
        const int a = blockIdx.x * 8 + warp;
        const float sqa = s_sq[a];
        const int la = s_lab[a];

        // reg idx = g*4+e  ->  j = g*128 + lane*4 + e
        float d[16];
        int lb[16];
#pragma unroll
        for (int g = 0; g < 4; g++) {
            const int j0 = g * 128 + lane * 4;
            float4 p = *reinterpret_cast<const float4*>(&g_Dm[(size_t)a * NB + j0]);
            float4 sq4 = *reinterpret_cast<const float4*>(&s_sq[j0]);
            int4 lb4 = *reinterpret_cast<const int4*>(&s_lab[j0]);
            d[g * 4 + 0] = fmaxf(sqa + sq4.x - 2.f * p.x, 0.f);
            d[g * 4 + 1] = fmaxf(sqa + sq4.y - 2.f * p.y, 0.f);
            d[g * 4 + 2] = fmaxf(sqa + sq4.z - 2.f * p.z, 0.f);
            d[g * 4 + 3] = fmaxf(sqa + sq4.w - 2.f * p.w, 0.f);
            lb[g * 4 + 0] = lb4.x; lb[g * 4 + 1] = lb4.y;
            lb[g * 4 + 2] = lb4.z; lb[g * 4 + 3] = lb4.w;
        }

        float nmin = INF_F;
#pragma unroll
        for (int t = 0; t < 16; t++)
            if (lb[t] != la) nmin = fminf(nmin, d[t]);
#pragma unroll
        for (int o = 16; o > 0; o >>= 1)
            nmin = fminf(nmin, __shfl_xor_sync(0xFFFFFFFFu, nmin, o));

        float sum = 0.f;
        int cnt = 0;
        if (nmin < 1e29f) {
#pragma unroll 1
            for (int t = 0; t < 16; t++) {
                const int j = (t >> 2) * 128 + lane * 4 + (t & 3);
                unsigned m = __ballot_sync(0xFFFFFFFFu, (j > a) && (lb[t] == la));
                while (m) {
                    const int lp = __ffs(m) - 1;
                    m &= m - 1;
                    const float ap = __shfl_sync(0xFFFFFFFFu, d[t], lp);
                    const float apM = ap + MARGIN;
                    float smin = INF_F;
#pragma unroll
                    for (int tt = 0; tt < 16; tt++) {
                        bool semi = (lb[tt] != la) && (d[tt] > ap) && (d[tt] < apM);
                        if (semi) smin = fminf(smin, d[tt]);
                    }
#pragma unroll
                    for (int o = 16; o > 0; o >>= 1)
                        smin = fminf(smin, __shfl_xor_sync(0xFFFFFFFFu, smin, o));
                    const float negd = (smin < 1e29f) ? smin : nmin;
                    sum += fmaxf(ap - negd + MARGIN, 0.f);
                    cnt++;
                }
            }
        }
        if (lane == 0) {
            accll = __double2ll_rn((double)sum * 4294967296.0);
            cntll = cnt;
        }
    }
    if (lane == 0 && (accll | cntll)) {
        atomicAdd(&g_ctl.acc, (ull)accll);
        atomicAdd(&g_ctl.cnt, (ull)cntll);
    }

    __syncthreads();
    __threadfence();
    if (tid == 0) {
        const int o = atomicAdd(&g_ctl.done, 1);
        if (o == 63) {
            __threadfence();
            ull a = *(volatile ull*)&g_ctl.acc;
            ull c = *(volatile ull*)&g_ctl.cnt;
            out[0] = (float)(((double)a / 4294967296.0) / (double)(c ? c : 1ull));
        }
    }
}

extern "C" void kernel_launch(void* const* d_in, const int* in_sizes, int n_in,
                              void* d_out, int out_size) {
    const float* emb = (const float*)d_in[0];
    const int* labels = (const int*)d_in[1];
    float* out = (float*)d_out;

    cudaFuncSetAttribute(k_gemm, cudaFuncAttributeMaxDynamicSharedMemorySize,
                         100 * 1024);

    void* ctl = nullptr;
    cudaGetSymbolAddress(&ctl, g_ctl);
    cudaMemsetAsync(ctl, 0, sizeof(Ctl));

    dim3 grid(4, 4, NSPLIT);
    k_gemm<<<grid, 256, 96 * 1024>>>(emb);
    k_prep<<<NB, 128>>>();
    k_mine<<<64, 256>>>(labels, out);
}

// round 10
// speedup vs baseline: 1.4195x; 1.3195x over previous
#include <cuda_runtime.h>
#include <cuda_bf16.h>
#include <cstdint>

#define NB 512
#define ND 512
#define MARGIN 0.2f
#define INF_F 1e30f
#define NSPLIT 8        // K splits of 64
#define KB 64           // K per block

typedef unsigned long long ull;

// ---------------- scratch ----------------
__device__ float g_P[NSPLIT][NB * NB];   // split-K partial dot products (8 MB)
__device__ float g_sq[NB];               // row squared norms (diag sums)

struct Ctl {
    unsigned long long acc;   // fixed-point loss sum (x 2^32)
    unsigned long long cnt;   // valid pair count
    int done;
    int pad;
};
__device__ Ctl g_ctl;

// ---------------- f32x2 helpers ----------------
__device__ __forceinline__ ull dup2(float x) {
    ull r;
    asm("mov.b64 %0, {%1, %1};" : "=l"(r) : "r"(__float_as_uint(x)));
    return r;
}
__device__ __forceinline__ void fma2(ull& d, ull a, ull b) {
    asm("fma.rn.f32x2 %0, %1, %2, %0;" : "+l"(d) : "l"(a), "l"(b));
}
__device__ __forceinline__ void unpk(ull v, float& lo, float& hi) {
    unsigned l, h;
    asm("mov.b64 {%0, %1}, %2;" : "=r"(l), "=r"(h) : "l"(v));
    lo = __uint_as_float(l);
    hi = __uint_as_float(h);
}

// =====================================================================
// Kernel A: GEMM. grid (4,4,8), 256 threads, 64KB dynamic smem.
//   A,B both plain f32 [k][128]; per kk: 2x LDS.128 each (A broadcast,
//   B 16B/lane contiguous) -> 16 wavefronts/warp/kk, zero conflicts.
// =====================================================================
__global__ void __launch_bounds__(256, 1)
k_gemm(const float* __restrict__ E) {
    extern __shared__ float smem[];
    float (*As)[128] = reinterpret_cast<float(*)[128]>(smem);            // 32 KB
    float (*Bs)[128] = reinterpret_cast<float(*)[128]>(smem + KB * 128); // 32 KB

    const int tid = threadIdx.x;
    const int bj = blockIdx.x, bi = blockIdx.y, bz = blockIdx.z;
    const int lane = tid & 31, warp = tid >> 5;

    // ---------- stage tiles (transposed, conflict-free stores) ----------
    {
        const int r = tid & 127;
        const int half = tid >> 7;
        const float* Ag = E + (size_t)(bi * 128 + r) * ND + bz * KB + half * 32;
        const float* Bg = E + (size_t)(bj * 128 + r) * ND + bz * KB + half * 32;
#pragma unroll
        for (int i = 0; i < 8; i++) {
            const int k = half * 32 + i * 4;
            float4 va = *reinterpret_cast<const float4*>(Ag + i * 4);
            float4 vb = *reinterpret_cast<const float4*>(Bg + i * 4);
            As[k + 0][r] = va.x; As[k + 1][r] = va.y;
            As[k + 2][r] = va.z; As[k + 3][r] = va.w;
            Bs[k + 0][r] = vb.x; Bs[k + 1][r] = vb.y;
            Bs[k + 2][r] = vb.z; Bs[k + 3][r] = vb.w;
        }
    }
    __syncthreads();

    // ---------- compute: 8x8 per thread ----------
    const int wr = warp >> 1, wc = warp & 1;
    const int ly = lane >> 3, lx = lane & 7;
    const int rbase = wr * 32 + ly * 8;
    const int cbase = wc * 64 + lx * 4;

    ull acc[4][8];
#pragma unroll
    for (int i = 0; i < 4; i++)
#pragma unroll
        for (int j = 0; j < 8; j++) acc[i][j] = 0ull;

#pragma unroll 4
    for (int kk = 0; kk < KB; kk++) {
        // A: 2x LDS.128 (broadcast within each 8-lane phase)
        ulonglong2 A01 = *reinterpret_cast<const ulonglong2*>(&As[kk][rbase + 0]);
        ulonglong2 A23 = *reinterpret_cast<const ulonglong2*>(&As[kk][rbase + 4]);
        // B: 2x LDS.128 (16B/lane, contiguous per phase)
        float4 bv0 = *reinterpret_cast<const float4*>(&Bs[kk][cbase]);
        float4 bv1 = *reinterpret_cast<const float4*>(&Bs[kk][cbase + 32]);
        ull b0 = dup2(bv0.x), b1 = dup2(bv0.y), b2 = dup2(bv0.z), b3 = dup2(bv0.w);
        ull b4 = dup2(bv1.x), b5 = dup2(bv1.y), b6 = dup2(bv1.z), b7 = dup2(bv1.w);
        fma2(acc[0][0], A01.x, b0); fma2(acc[1][0], A01.y, b0);
        fma2(acc[2][0], A23.x, b0); fma2(acc[3][0], A23.y, b0);
        fma2(acc[0][1], A01.x, b1); fma2(acc[1][1], A01.y, b1);
        fma2(acc[2][1], A23.x, b1); fma2(acc[3][1], A23.y, b1);
        fma2(acc[0][2], A01.x, b2); fma2(acc[1][2], A01.y, b2);
        fma2(acc[2][2], A23.x, b2); fma2(acc[3][2], A23.y, b2);
        fma2(acc[0][3], A01.x, b3); fma2(acc[1][3], A01.y, b3);
        fma2(acc[2][3], A23.x, b3); fma2(acc[3][3], A23.y, b3);
        fma2(acc[0][4], A01.x, b4); fma2(acc[1][4], A01.y, b4);
        fma2(acc[2][4], A23.x, b4); fma2(acc[3][4], A23.y, b4);
        fma2(acc[0][5], A01.x, b5); fma2(acc[1][5], A01.y, b5);
        fma2(acc[2][5], A23.x, b5); fma2(acc[3][5], A23.y, b5);
        fma2(acc[0][6], A01.x, b6); fma2(acc[1][6], A01.y, b6);
        fma2(acc[2][6], A23.x, b6); fma2(acc[3][6], A23.y, b6);
        fma2(acc[0][7], A01.x, b7); fma2(acc[1][7], A01.y, b7);
        fma2(acc[2][7], A23.x, b7); fma2(acc[3][7], A23.y, b7);
    }

    // ---------- epilogue ----------
    {
        float* dst = g_P[bz];
        const int c0 = bj * 128 + cbase;
#pragma unroll
        for (int rp = 0; rp < 4; rp++) {
            float lo[8], hi[8];
#pragma unroll
            for (int j = 0; j < 8; j++) unpk(acc[rp][j], lo[j], hi[j]);
            const int r0 = bi * 128 + rbase + 2 * rp;
            float* d0 = &dst[(size_t)r0 * NB + c0];
            float* d1 = &dst[(size_t)(r0 + 1) * NB + c0];
            *reinterpret_cast<float4*>(d0)      = make_float4(lo[0], lo[1], lo[2], lo[3]);
            *reinterpret_cast<float4*>(d0 + 32) = make_float4(lo[4], lo[5], lo[6], lo[7]);
            *reinterpret_cast<float4*>(d1)      = make_float4(hi[0], hi[1], hi[2], hi[3]);
            *reinterpret_cast<float4*>(d1 + 32) = make_float4(hi[4], hi[5], hi[6], hi[7]);
        }
    }
}

// =====================================================================
// Kernel B: diag sums -> g_sq. grid 4 x 128 (one thread per row).
// =====================================================================
__global__ void k_diag(void) {
    const int r = blockIdx.x * 128 + threadIdx.x;
    float s = 0.f;
#pragma unroll
    for (int z = 0; z < NSPLIT; z++) s += g_P[z][(size_t)r * NB + r];
    g_sq[r] = s;
}

// =====================================================================
// Kernel C: block-per-anchor mining. grid 512 x 128.
//   Each block folds its anchor's row across 8 splits into smem, then
//   4 warps mine (warp w owns j in [w*128,(w+1)*128) for positives).
// =====================================================================
__global__ void __launch_bounds__(128, 8)
k_mine(const int* __restrict__ labels, float* __restrict__ out) {
    __shared__ float s_d[NB];
    __shared__ int s_lab[NB];
    __shared__ float s_nm[4];
    __shared__ float s_nmin;

    const int a = blockIdx.x;
    const int tid = threadIdx.x;
    const int lane = tid & 31, warp = tid >> 5;

    const float sqa = g_sq[a];

    // fold row a across splits; compute distances into smem
    {
        const int j0 = tid * 4;
        float4 p = make_float4(0.f, 0.f, 0.f, 0.f);
#pragma unroll
        for (int z = 0; z < NSPLIT; z++) {
            float4 v = *reinterpret_cast<const float4*>(&g_P[z][(size_t)a * NB + j0]);
            p.x += v.x; p.y += v.y; p.z += v.z; p.w += v.w;
        }
        float4 sq4 = *reinterpret_cast<const float4*>(&g_sq[j0]);
        s_d[j0 + 0] = fmaxf(sqa + sq4.x - 2.f * p.x, 0.f);
        s_d[j0 + 1] = fmaxf(sqa + sq4.y - 2.f * p.y, 0.f);
        s_d[j0 + 2] = fmaxf(sqa + sq4.z - 2.f * p.z, 0.f);
        s_d[j0 + 3] = fmaxf(sqa + sq4.w - 2.f * p.w, 0.f);
        *reinterpret_cast<int4*>(&s_lab[j0]) =
            *reinterpret_cast<const int4*>(&labels[j0]);
    }
    __syncthreads();

    const int la = s_lab[a];

    // per-warp register copies: d[t] = s_d[t*32+lane]
    float d[16];
    int lb[16];
#pragma unroll
    for (int t = 0; t < 16; t++) {
        d[t] = s_d[t * 32 + lane];
        lb[t] = s_lab[t * 32 + lane];
    }

    // block-wide min over negatives (fmin: order-independent)
    {
        float nm = INF_F;
#pragma unroll
        for (int t = 0; t < 16; t++)
            if (lb[t] != la) nm = fminf(nm, d[t]);
#pragma unroll
        for (int o = 16; o > 0; o >>= 1)
            nm = fminf(nm, __shfl_xor_sync(0xFFFFFFFFu, nm, o));
        if (lane == 0) s_nm[warp] = nm;
    }
    __syncthreads();
    if (tid == 0)
        s_nmin = fminf(fminf(s_nm[0], s_nm[1]), fminf(s_nm[2], s_nm[3]));
    __syncthreads();
    const float nmin = s_nmin;

    long long accll = 0, cntll = 0;
    if (nmin < 1e29f) {
        float sum = 0.f;
        int cnt = 0;
        // warp w scans its j-range [w*128, (w+1)*128) for positives
#pragma unroll 1
        for (int tt0 = 0; tt0 < 4; tt0++) {
            const int t = warp * 4 + tt0;
            const int j = t * 32 + lane;
            unsigned m = __ballot_sync(0xFFFFFFFFu, (j > a) && (lb[t] == la));
            while (m) {
                const int lp = __ffs(m) - 1;
                m &= m - 1;
                const float ap = __shfl_sync(0xFFFFFFFFu, d[t], lp);
                const float apM = ap + MARGIN;
                float smin = INF_F;
#pragma unroll
                for (int q = 0; q < 16; q++) {
                    bool semi = (lb[q] != la) && (d[q] > ap) && (d[q] < apM);
                    if (semi) smin = fminf(smin, d[q]);
                }
#pragma unroll
                for (int o = 16; o > 0; o >>= 1)
                    smin = fminf(smin, __shfl_xor_sync(0xFFFFFFFFu, smin, o));
                const float negd = (smin < 1e29f) ? smin : nmin;
                sum += fmaxf(ap - negd + MARGIN, 0.f);
                cnt++;
            }
        }
        if (lane == 0 && cnt) {
            accll = __double2ll_rn((double)sum * 4294967296.0);
            cntll = cnt;
        }
    }
    if (lane == 0 && (accll | cntll)) {
        atomicAdd(&g_ctl.acc, (ull)accll);
        atomicAdd(&g_ctl.cnt, (ull)cntll);
    }

    // finalize: last block writes the scalar
    __syncthreads();
    __threadfence();
    if (tid == 0) {
        const int o = atomicAdd(&g_ctl.done, 1);
        if (o == NB - 1) {
            __threadfence();
            ull av = *(volatile ull*)&g_ctl.acc;
            ull cv = *(volatile ull*)&g_ctl.cnt;
            out[0] = (float)(((double)av / 4294967296.0) / (double)(cv ? cv : 1ull));
        }
    }
}

extern "C" void kernel_launch(void* const* d_in, const int* in_sizes, int n_in,
                              void* d_out, int out_size) {
    const float* emb = (const float*)d_in[0];
    const int* labels = (const int*)d_in[1];
    float* out = (float*)d_out;

    cudaFuncSetAttribute(k_gemm, cudaFuncAttributeMaxDynamicSharedMemorySize,
                         72 * 1024);

    void* ctl = nullptr;
    cudaGetSymbolAddress(&ctl, g_ctl);
    cudaMemsetAsync(ctl, 0, sizeof(Ctl));

    dim3 grid(4, 4, NSPLIT);
    k_gemm<<<grid, 256, 64 * 1024>>>(emb);
    k_diag<<<4, 128>>>();
    k_mine<<<NB, 128>>>(labels, out);
}